// round 10
// baseline (speedup 1.0000x reference)
#include <cuda_runtime.h>
#include <cuda_fp16.h>
#include <cstdint>

constexpr int Bb = 2, Ss = 2048, Dd = 1024, Hh = 16, HD = 64;
constexpr int Mm = Bb * Ss;  // 4096

// fp16 scratch (allocation-free rule: __device__ globals)
__device__ __align__(256) __half g_xh[Mm * Dd],  g_xl[Mm * Dd];   // x 2-term
__device__ __align__(256) __half g_W[4 * Dd * Dd];                // W single
__device__ __align__(256) __half g_Qh[Mm * Dd],  g_Ql[Mm * Dd];   // Q 2-term [B,H,S,HD]
__device__ __align__(256) __half g_Kh[Mm * Dd];                   // K single
__device__ __align__(256) __half g_Vh[Mm * Dd],  g_Vl[Mm * Dd];   // V 2-term
__device__ __align__(256) __half g_ctxh[Mm * Dd], g_ctxl[Mm * Dd]; // ctx 2-term [B*S,D]

// ---------------------------------------------------------------------------
// helpers
// ---------------------------------------------------------------------------
__device__ __forceinline__ uint32_t smaddr(const void* p) {
    uint32_t a;
    asm("{ .reg .u64 t; cvta.to.shared.u64 t, %1; cvt.u32.u64 %0, t; }"
        : "=r"(a) : "l"(p));
    return a;
}
// SW128 swizzle for 128B rows
__device__ __forceinline__ uint32_t swz(int r, int b) {
    return (uint32_t)(r * 128 + (b ^ ((r & 7) << 4)));
}
__device__ __forceinline__ void ldsm4(uint32_t* r, uint32_t a) {
    asm volatile("ldmatrix.sync.aligned.m8n8.x4.shared.b16 {%0,%1,%2,%3}, [%4];"
                 : "=r"(r[0]), "=r"(r[1]), "=r"(r[2]), "=r"(r[3]) : "r"(a));
}
__device__ __forceinline__ void ldsm4t(uint32_t* r, uint32_t a) {
    asm volatile("ldmatrix.sync.aligned.m8n8.x4.trans.shared.b16 {%0,%1,%2,%3}, [%4];"
                 : "=r"(r[0]), "=r"(r[1]), "=r"(r[2]), "=r"(r[3]) : "r"(a));
}
__device__ __forceinline__ void mma16816(float* c, const uint32_t* a, const uint32_t* b) {
    asm volatile(
        "mma.sync.aligned.m16n8k16.row.col.f32.f16.f16.f32 "
        "{%0,%1,%2,%3}, {%4,%5,%6,%7}, {%8,%9}, {%0,%1,%2,%3};"
        : "+f"(c[0]), "+f"(c[1]), "+f"(c[2]), "+f"(c[3])
        : "r"(a[0]), "r"(a[1]), "r"(a[2]), "r"(a[3]), "r"(b[0]), "r"(b[1]));
}
__device__ __forceinline__ float ex2f(float x) {
    float y;
    asm("ex2.approx.ftz.f32 %0, %1;" : "=f"(y) : "f"(x));
    return y;
}
__device__ __forceinline__ void cp16(uint32_t dst, const void* src) {
    asm volatile("cp.async.cg.shared.global [%0], [%1], 16;" :: "r"(dst), "l"(src));
}
#define CP_COMMIT() asm volatile("cp.async.commit_group;" ::: "memory")
#define CP_WAIT1()  asm volatile("cp.async.wait_group 1;" ::: "memory")
#define CP_WAIT0()  asm volatile("cp.async.wait_group 0;" ::: "memory")

__device__ __forceinline__ uint32_t pack2h(float a, float b) {
    __half2 v = __floats2half2_rn(a, b);
    return *reinterpret_cast<uint32_t*>(&v);
}
__device__ __forceinline__ void split2h(float a, float b, uint32_t& h, uint32_t& l) {
    __half2 hv = __floats2half2_rn(a, b);
    float2 hf = __half22float2(hv);
    __half2 lv = __floats2half2_rn(a - hf.x, b - hf.y);
    h = *reinterpret_cast<uint32_t*>(&hv);
    l = *reinterpret_cast<uint32_t*>(&lv);
}

// ---------------------------------------------------------------------------
// 1) convert: x -> fp16 2-term; W -> fp16 single
// ---------------------------------------------------------------------------
__global__ __launch_bounds__(256) void convert_split(const float* __restrict__ x,
                                                     const float* __restrict__ Wq,
                                                     const float* __restrict__ Wk,
                                                     const float* __restrict__ Wv,
                                                     const float* __restrict__ Wo)
{
    const int NX = Mm * Dd / 4;
    const int NW = Dd * Dd / 4;
    int i = blockIdx.x * 256 + threadIdx.x;
    if (i >= NX + 4 * NW) return;

    if (i < NX) {
        float4 v = ((const float4*)x)[i];
        uint32_t h01, l01, h23, l23;
        split2h(v.x, v.y, h01, l01);
        split2h(v.z, v.w, h23, l23);
        uint2 hv = {h01, h23}, lv = {l01, l23};
        *(uint2*)&g_xh[(size_t)i * 4] = hv;
        *(uint2*)&g_xl[(size_t)i * 4] = lv;
    } else {
        int j = i - NX;
        int w = j / NW;
        int off = j % NW;
        const float* s = (w == 0) ? Wq : (w == 1) ? Wk : (w == 2) ? Wv : Wo;
        float4 v = ((const float4*)s)[off];
        uint2 hv = {pack2h(v.x, v.y), pack2h(v.z, v.w)};
        *(uint2*)&g_W[(size_t)w * Dd * Dd + (size_t)off * 4] = hv;
    }
}

// ---------------------------------------------------------------------------
// 2) GEMM v7: as v6 but MMA order interleaved across acc tiles
//    (same-accumulator distance 1 -> 4) to break the RAW chain.
// ---------------------------------------------------------------------------
constexpr int G_STAGE = 49152;
constexpr int GEMM_SMEM = 2 * G_STAGE;     // 98304 B -> 2 CTAs/SM

template <int MODE>
__global__ __launch_bounds__(256, 2) void gemm_tc(const float* __restrict__ bias,
                                                  float* __restrict__ outd)
{
    extern __shared__ char smc[];
    const uint32_t sb = smaddr(smc);
    const int tid = threadIdx.x, lane = tid & 31, wid = tid >> 5;
    const int wm = wid & 1, wn = wid >> 1;           // warp grid 2m x 4n
    const int m0 = blockIdx.y * 128, n0 = blockIdx.x * 128;
    const int z = (MODE == 0) ? blockIdx.z : 3;

    const __half* pAh = (MODE == 0) ? g_xh : g_ctxh;
    const __half* pAl = (MODE == 0) ? g_xl : g_ctxl;
    const __half* pB  = g_W + (size_t)z * Dd * Dd;

    const int q  = tid & 7;
    const int rs = tid >> 3;

    auto issue = [&](int ch, int st) {
        const int k0 = ch * 64 + q * 8;
        const uint32_t stb = sb + (uint32_t)st * G_STAGE;
#pragma unroll
        for (int j = 0; j < 4; j++) {
            int row = j * 32 + rs;
            uint32_t so = swz(row, q * 16);
            cp16(stb + so,         pAh + (size_t)(m0 + row) * Dd + k0);
            cp16(stb + 16384 + so, pAl + (size_t)(m0 + row) * Dd + k0);
            cp16(stb + 32768 + so, pB  + (size_t)(n0 + row) * Dd + k0);
        }
        CP_COMMIT();
    };

    float acc[4][4][4];
#pragma unroll
    for (int a = 0; a < 4; a++)
#pragma unroll
        for (int b = 0; b < 4; b++)
#pragma unroll
            for (int c = 0; c < 4; c++) acc[a][b][c] = 0.0f;

    issue(0, 0);
    issue(1, 1);

    constexpr int NCH = Dd / 64;   // 16
    for (int ch = 0; ch < NCH; ch++) {
        if (ch < NCH - 1) CP_WAIT1(); else CP_WAIT0();
        __syncthreads();

        const uint32_t aAh = sb + (uint32_t)(ch & 1) * G_STAGE;
        const uint32_t aAl = aAh + 16384;
        const uint32_t aB  = aAh + 32768;

#pragma unroll
        for (int ks = 0; ks < 4; ks++) {
            uint32_t bh[2][4];
            const int g = lane >> 3;
            const int brow = wn * 32 + ((g >> 1) << 3) + (lane & 7);
            const int bqb = ks * 32 + ((g & 1) << 4);
#pragma unroll
            for (int p = 0; p < 2; p++)
                ldsm4(bh[p], aB + swz(brow + p * 16, bqb));

            const int arow = wm * 64 + (lane & 15);
            const int aqb = ks * 32 + ((lane >> 4) << 4);
#pragma unroll
            for (int mt = 0; mt < 4; mt++) {
                uint32_t ah[4], al[4];
                int r = arow + mt * 16;
                ldsm4(ah, aAh + swz(r, aqb));
                ldsm4(al, aAl + swz(r, aqb));
                // hi pass over all 4 acc tiles, then lo pass: RAW distance 4
                mma16816(acc[mt][0], ah, &bh[0][0]);
                mma16816(acc[mt][1], ah, &bh[0][2]);
                mma16816(acc[mt][2], ah, &bh[1][0]);
                mma16816(acc[mt][3], ah, &bh[1][2]);
                mma16816(acc[mt][0], al, &bh[0][0]);
                mma16816(acc[mt][1], al, &bh[0][2]);
                mma16816(acc[mt][2], al, &bh[1][0]);
                mma16816(acc[mt][3], al, &bh[1][2]);
            }
        }
        __syncthreads();
        if (ch + 2 < NCH) issue(ch + 2, ch & 1);
    }

    // epilogue
    const int g4 = lane >> 2, q2 = (lane & 3) * 2;
    if (MODE == 0) {
#pragma unroll
        for (int mt = 0; mt < 4; mt++)
#pragma unroll
            for (int nt = 0; nt < 4; nt++) {
                int r0 = m0 + wm * 64 + mt * 16 + g4;
                int n  = n0 + wn * 32 + nt * 8 + q2;
                int b = r0 >> 11, s = r0 & 2047;
                int h = n >> 6,  d = n & 63;
                size_t i0 = (((size_t)(b * Hh + h)) * Ss + s) * HD + d;
                size_t i1 = i0 + (size_t)8 * HD;
                if (z == 1) {   // K single fp16
                    *(uint32_t*)&g_Kh[i0] = pack2h(acc[mt][nt][0], acc[mt][nt][1]);
                    *(uint32_t*)&g_Kh[i1] = pack2h(acc[mt][nt][2], acc[mt][nt][3]);
                } else {        // Q or V: 2-term fp16
                    __half* oh = (z == 0) ? g_Qh : g_Vh;
                    __half* ol = (z == 0) ? g_Ql : g_Vl;
                    uint32_t hh, ll;
                    split2h(acc[mt][nt][0], acc[mt][nt][1], hh, ll);
                    *(uint32_t*)&oh[i0] = hh; *(uint32_t*)&ol[i0] = ll;
                    split2h(acc[mt][nt][2], acc[mt][nt][3], hh, ll);
                    *(uint32_t*)&oh[i1] = hh; *(uint32_t*)&ol[i1] = ll;
                }
            }
    } else {
#pragma unroll
        for (int mt = 0; mt < 4; mt++)
#pragma unroll
            for (int nt = 0; nt < 4; nt++) {
                int r0 = m0 + wm * 64 + mt * 16 + g4;
                int n  = n0 + wn * 32 + nt * 8 + q2;
                float b0 = bias[n], b1 = bias[n + 1];
                float2 v0 = {acc[mt][nt][0] + b0, acc[mt][nt][1] + b1};
                float2 v1 = {acc[mt][nt][2] + b0, acc[mt][nt][3] + b1};
                *(float2*)&outd[(size_t)r0 * Dd + n] = v0;
                *(float2*)&outd[(size_t)(r0 + 8) * Dd + n] = v1;
            }
    }
}

// ---------------------------------------------------------------------------
// 3) flash v6: as v5 but MMA order interleaved (RAW distance 4) in QK and PV.
// ---------------------------------------------------------------------------
constexpr int F_Q   = 16384;
constexpr int F_KV  = 8192;
constexpr int FLASH_SMEM = 2 * F_Q + 6 * F_KV;   // 81920

__global__ __launch_bounds__(256, 2) void flash_tc()
{
    extern __shared__ char fsc[];
    const uint32_t sb = smaddr(fsc);

    const int tid = threadIdx.x, lane = tid & 31, wid = tid >> 5;
    const int qt = gridDim.x - 1 - blockIdx.x;     // heavy tiles first
    const int bhi = blockIdx.y;
    const size_t base = (size_t)bhi * Ss * HD;
    const float SCL = 0.125f * 1.4426950408889634f;

    const __half* ksrc[3] = {g_Kh + base, g_Vh + base, g_Vl + base};

    const int q  = tid & 7;
    const int rs = tid >> 3;

    auto issue_kv = [&](int kt, int st) {
        const uint32_t stb = sb + 2 * F_Q + (uint32_t)st * 3 * F_KV;
#pragma unroll
        for (int a = 0; a < 3; a++) {
#pragma unroll
            for (int j = 0; j < 2; j++) {
                int row = j * 32 + rs;
                cp16(stb + (uint32_t)a * F_KV + swz(row, q * 16),
                     ksrc[a] + (size_t)(kt * 64 + row) * HD + q * 8);
            }
        }
        CP_COMMIT();
    };

    const int ktmax = 2 * qt + 1;
    issue_kv(0, 0);

#pragma unroll
    for (int j = 0; j < 4; j++) {
        int row = j * 32 + rs;
        size_t go = base + (size_t)(qt * 128 + row) * HD + q * 8;
        *(uint4*)(fsc + swz(row, q * 16))       = *(const uint4*)&g_Qh[go];
        *(uint4*)(fsc + F_Q + swz(row, q * 16)) = *(const uint4*)&g_Ql[go];
    }

    float m0_ = -1e30f, m1_ = -1e30f, l0_ = 0.f, l1_ = 0.f;
    float o[8][4];
#pragma unroll
    for (int t = 0; t < 8; t++)
#pragma unroll
        for (int c = 0; c < 4; c++) o[t][c] = 0.f;

    const uint32_t aQh = sb, aQl = sb + F_Q;

    for (int kt = 0; kt <= ktmax; kt++) {
        if (kt < ktmax) { issue_kv(kt + 1, (kt + 1) & 1); CP_WAIT1(); }
        else            { CP_WAIT0(); }
        __syncthreads();

        const uint32_t stb = sb + 2 * F_Q + (uint32_t)(kt & 1) * 3 * F_KV;
        const uint32_t aK  = stb;
        const uint32_t aVh = stb + F_KV, aVl = stb + 2 * F_KV;

        // S = Q K^T (2-term), K-row pairs, hi pass then lo pass (distance 4)
        float s[8][4];
#pragma unroll
        for (int t = 0; t < 8; t++)
#pragma unroll
            for (int c = 0; c < 4; c++) s[t][c] = 0.f;

#pragma unroll
        for (int ks = 0; ks < 4; ks++) {
            uint32_t qh[4], ql[4];
            const int arow = wid * 16 + (lane & 15);
            const int aqb  = ks * 32 + ((lane >> 4) << 4);
            ldsm4(qh, aQh + swz(arow, aqb));
            ldsm4(ql, aQl + swz(arow, aqb));
            const int g = lane >> 3;
            const int br = ((g >> 1) << 3) + (lane & 7);
            const int bqb = ks * 32 + ((g & 1) << 4);
#pragma unroll
            for (int pp = 0; pp < 2; pp++) {
                uint32_t k0r[4], k1r[4];
                ldsm4(k0r, aK + swz(br + (2 * pp)     * 16, bqb));
                ldsm4(k1r, aK + swz(br + (2 * pp + 1) * 16, bqb));
                mma16816(s[4 * pp + 0], qh, &k0r[0]);
                mma16816(s[4 * pp + 1], qh, &k0r[2]);
                mma16816(s[4 * pp + 2], qh, &k1r[0]);
                mma16816(s[4 * pp + 3], qh, &k1r[2]);
                mma16816(s[4 * pp + 0], ql, &k0r[0]);
                mma16816(s[4 * pp + 1], ql, &k0r[2]);
                mma16816(s[4 * pp + 2], ql, &k1r[0]);
                mma16816(s[4 * pp + 3], ql, &k1r[2]);
            }
        }

        // scale (base-2) + causal mask (last two k-tiles only)
        const int r0g = qt * 128 + wid * 16 + (lane >> 2);
        const int r1g = r0g + 8;
        const bool needmask = (kt >= 2 * qt);
        float mx0 = -1e30f, mx1 = -1e30f;
#pragma unroll
        for (int t = 0; t < 8; t++) {
            int cg = kt * 64 + t * 8 + (lane & 3) * 2;
            float v0 = s[t][0] * SCL, v1 = s[t][1] * SCL;
            float v2 = s[t][2] * SCL, v3 = s[t][3] * SCL;
            if (needmask) {
                if (cg     > r0g) v0 = -1e30f;
                if (cg + 1 > r0g) v1 = -1e30f;
                if (cg     > r1g) v2 = -1e30f;
                if (cg + 1 > r1g) v3 = -1e30f;
            }
            s[t][0] = v0; s[t][1] = v1; s[t][2] = v2; s[t][3] = v3;
            mx0 = fmaxf(mx0, fmaxf(v0, v1));
            mx1 = fmaxf(mx1, fmaxf(v2, v3));
        }
        mx0 = fmaxf(mx0, __shfl_xor_sync(0xffffffffu, mx0, 1));
        mx0 = fmaxf(mx0, __shfl_xor_sync(0xffffffffu, mx0, 2));
        mx1 = fmaxf(mx1, __shfl_xor_sync(0xffffffffu, mx1, 1));
        mx1 = fmaxf(mx1, __shfl_xor_sync(0xffffffffu, mx1, 2));
        float nm0 = fmaxf(m0_, mx0), nm1 = fmaxf(m1_, mx1);
        float al0 = ex2f(m0_ - nm0), al1 = ex2f(m1_ - nm1);
        float sum0 = 0.f, sum1 = 0.f;
#pragma unroll
        for (int t = 0; t < 8; t++) {
            float p0 = ex2f(s[t][0] - nm0), p1 = ex2f(s[t][1] - nm0);
            float p2 = ex2f(s[t][2] - nm1), p3 = ex2f(s[t][3] - nm1);
            s[t][0] = p0; s[t][1] = p1; s[t][2] = p2; s[t][3] = p3;
            sum0 += p0 + p1; sum1 += p2 + p3;
        }
        sum0 += __shfl_xor_sync(0xffffffffu, sum0, 1);
        sum0 += __shfl_xor_sync(0xffffffffu, sum0, 2);
        sum1 += __shfl_xor_sync(0xffffffffu, sum1, 1);
        sum1 += __shfl_xor_sync(0xffffffffu, sum1, 2);
        l0_ = l0_ * al0 + sum0;
        l1_ = l1_ * al1 + sum1;
        m0_ = nm0; m1_ = nm1;
#pragma unroll
        for (int t = 0; t < 8; t++) {
            o[t][0] *= al0; o[t][1] *= al0;
            o[t][2] *= al1; o[t][3] *= al1;
        }

        // pack P (single fp16) into A-fragments
        uint32_t pa[4][4];
#pragma unroll
        for (int t = 0; t < 4; t++) {
            pa[t][0] = pack2h(s[2 * t][0],     s[2 * t][1]);
            pa[t][1] = pack2h(s[2 * t][2],     s[2 * t][3]);
            pa[t][2] = pack2h(s[2 * t + 1][0], s[2 * t + 1][1]);
            pa[t][3] = pack2h(s[2 * t + 1][2], s[2 * t + 1][3]);
        }

        // O += P V (2-term), V-col pairs, hi pass then lo pass (distance 4)
        const int g = lane >> 3;
        const int vr = ((g & 1) << 3) + (lane & 7);
        const int vcb = (lane >= 16) ? 16 : 0;
#pragma unroll
        for (int t = 0; t < 4; t++) {
            int r = t * 16 + vr;
#pragma unroll
            for (int dpp = 0; dpp < 2; dpp++) {
                uint32_t vAh[4], vAl[4], vBh[4], vBl[4];
                int bA = (2 * dpp)     * 32 + vcb;
                int bB = (2 * dpp + 1) * 32 + vcb;
                ldsm4t(vAh, aVh + swz(r, bA));
                ldsm4t(vBh, aVh + swz(r, bB));
                ldsm4t(vAl, aVl + swz(r, bA));
                ldsm4t(vBl, aVl + swz(r, bB));
                mma16816(o[4 * dpp + 0], pa[t], &vAh[0]);
                mma16816(o[4 * dpp + 1], pa[t], &vAh[2]);
                mma16816(o[4 * dpp + 2], pa[t], &vBh[0]);
                mma16816(o[4 * dpp + 3], pa[t], &vBh[2]);
                mma16816(o[4 * dpp + 0], pa[t], &vAl[0]);
                mma16816(o[4 * dpp + 1], pa[t], &vAl[2]);
                mma16816(o[4 * dpp + 2], pa[t], &vBl[0]);
                mma16816(o[4 * dpp + 3], pa[t], &vBl[2]);
            }
        }
        __syncthreads();
    }

    // epilogue: normalize, 2-term fp16 ctx [B*S, D]
    const int b = bhi >> 4, h = bhi & 15;
    const float i0 = 1.f / l0_, i1 = 1.f / l1_;
    const int r0 = qt * 128 + wid * 16 + (lane >> 2);
    const size_t row0 = (size_t)(b * Ss + r0) * Dd;
    const size_t row1 = row0 + (size_t)8 * Dd;
#pragma unroll
    for (int dt = 0; dt < 8; dt++) {
        int d = h * 64 + dt * 8 + (lane & 3) * 2;
        uint32_t hh, ll;
        split2h(o[dt][0] * i0, o[dt][1] * i0, hh, ll);
        *(uint32_t*)&g_ctxh[row0 + d] = hh;
        *(uint32_t*)&g_ctxl[row0 + d] = ll;
        split2h(o[dt][2] * i1, o[dt][3] * i1, hh, ll);
        *(uint32_t*)&g_ctxh[row1 + d] = hh;
        *(uint32_t*)&g_ctxl[row1 + d] = ll;
    }
}

// ---------------------------------------------------------------------------
extern "C" void kernel_launch(void* const* d_in, const int* in_sizes, int n_in,
                              void* d_out, int out_size)
{
    const float* x  = (const float*)d_in[0];
    const float* Wq = (const float*)d_in[1];
    const float* Wk = (const float*)d_in[2];
    const float* Wv = (const float*)d_in[3];
    const float* Wo = (const float*)d_in[4];
    const float* bo = (const float*)d_in[5];
    float* out = (float*)d_out;

    cudaFuncSetAttribute(gemm_tc<0>, cudaFuncAttributeMaxDynamicSharedMemorySize,
                         GEMM_SMEM);
    cudaFuncSetAttribute(gemm_tc<1>, cudaFuncAttributeMaxDynamicSharedMemorySize,
                         GEMM_SMEM);
    cudaFuncSetAttribute(flash_tc, cudaFuncAttributeMaxDynamicSharedMemorySize,
                         FLASH_SMEM);

    convert_split<<<(Mm * Dd / 4 + 4 * Dd * Dd / 4 + 255) / 256, 256>>>(
        x, Wq, Wk, Wv, Wo);

    gemm_tc<0><<<dim3(Dd / 128, Mm / 128, 3), 256, GEMM_SMEM>>>(nullptr, nullptr);

    flash_tc<<<dim3(Ss / 128, Bb * Hh), 256, FLASH_SMEM>>>();

    gemm_tc<1><<<dim3(Dd / 128, Mm / 128, 1), 256, GEMM_SMEM>>>(bo, out);
}

// round 11
// speedup vs baseline: 1.5331x; 1.5331x over previous
#include <cuda_runtime.h>
#include <cuda_fp16.h>
#include <cstdint>

constexpr int Bb = 2, Ss = 2048, Dd = 1024, Hh = 16, HD = 64;
constexpr int Mm = Bb * Ss;  // 4096

// fp16 scratch (allocation-free rule: __device__ globals)
__device__ __align__(256) __half g_xh[Mm * Dd],  g_xl[Mm * Dd];   // x 2-term
__device__ __align__(256) __half g_W[4 * Dd * Dd];                // W single
__device__ __align__(256) __half g_Qh[Mm * Dd],  g_Ql[Mm * Dd];   // Q 2-term [B,H,S,HD]
__device__ __align__(256) __half g_Kh[Mm * Dd];                   // K single
__device__ __align__(256) __half g_Vh[Mm * Dd],  g_Vl[Mm * Dd];   // V 2-term
__device__ __align__(256) __half g_ctxh[Mm * Dd], g_ctxl[Mm * Dd]; // ctx 2-term [B*S,D]

// ---------------------------------------------------------------------------
// helpers
// ---------------------------------------------------------------------------
__device__ __forceinline__ uint32_t smaddr(const void* p) {
    uint32_t a;
    asm("{ .reg .u64 t; cvta.to.shared.u64 t, %1; cvt.u32.u64 %0, t; }"
        : "=r"(a) : "l"(p));
    return a;
}
// SW128 swizzle for 128B rows
__device__ __forceinline__ uint32_t swz(int r, int b) {
    return (uint32_t)(r * 128 + (b ^ ((r & 7) << 4)));
}
__device__ __forceinline__ void ldsm4(uint32_t* r, uint32_t a) {
    asm volatile("ldmatrix.sync.aligned.m8n8.x4.shared.b16 {%0,%1,%2,%3}, [%4];"
                 : "=r"(r[0]), "=r"(r[1]), "=r"(r[2]), "=r"(r[3]) : "r"(a));
}
__device__ __forceinline__ void ldsm4t(uint32_t* r, uint32_t a) {
    asm volatile("ldmatrix.sync.aligned.m8n8.x4.trans.shared.b16 {%0,%1,%2,%3}, [%4];"
                 : "=r"(r[0]), "=r"(r[1]), "=r"(r[2]), "=r"(r[3]) : "r"(a));
}
__device__ __forceinline__ void mma16816(float* c, const uint32_t* a, const uint32_t* b) {
    asm volatile(
        "mma.sync.aligned.m16n8k16.row.col.f32.f16.f16.f32 "
        "{%0,%1,%2,%3}, {%4,%5,%6,%7}, {%8,%9}, {%0,%1,%2,%3};"
        : "+f"(c[0]), "+f"(c[1]), "+f"(c[2]), "+f"(c[3])
        : "r"(a[0]), "r"(a[1]), "r"(a[2]), "r"(a[3]), "r"(b[0]), "r"(b[1]));
}
__device__ __forceinline__ float ex2f(float x) {
    float y;
    asm("ex2.approx.ftz.f32 %0, %1;" : "=f"(y) : "f"(x));
    return y;
}
__device__ __forceinline__ void cp16(uint32_t dst, const void* src) {
    asm volatile("cp.async.cg.shared.global [%0], [%1], 16;" :: "r"(dst), "l"(src));
}
#define CP_COMMIT() asm volatile("cp.async.commit_group;" ::: "memory")
#define CP_WAIT1()  asm volatile("cp.async.wait_group 1;" ::: "memory")
#define CP_WAIT0()  asm volatile("cp.async.wait_group 0;" ::: "memory")

__device__ __forceinline__ uint32_t pack2h(float a, float b) {
    __half2 v = __floats2half2_rn(a, b);
    return *reinterpret_cast<uint32_t*>(&v);
}
__device__ __forceinline__ void split2h(float a, float b, uint32_t& h, uint32_t& l) {
    __half2 hv = __floats2half2_rn(a, b);
    float2 hf = __half22float2(hv);
    __half2 lv = __floats2half2_rn(a - hf.x, b - hf.y);
    h = *reinterpret_cast<uint32_t*>(&hv);
    l = *reinterpret_cast<uint32_t*>(&lv);
}

// ---------------------------------------------------------------------------
// 1) convert: x -> fp16 2-term; W -> fp16 single
// ---------------------------------------------------------------------------
__global__ __launch_bounds__(256) void convert_split(const float* __restrict__ x,
                                                     const float* __restrict__ Wq,
                                                     const float* __restrict__ Wk,
                                                     const float* __restrict__ Wv,
                                                     const float* __restrict__ Wo)
{
    const int NX = Mm * Dd / 4;
    const int NW = Dd * Dd / 4;
    int i = blockIdx.x * 256 + threadIdx.x;
    if (i >= NX + 4 * NW) return;

    if (i < NX) {
        float4 v = ((const float4*)x)[i];
        uint32_t h01, l01, h23, l23;
        split2h(v.x, v.y, h01, l01);
        split2h(v.z, v.w, h23, l23);
        uint2 hv = {h01, h23}, lv = {l01, l23};
        *(uint2*)&g_xh[(size_t)i * 4] = hv;
        *(uint2*)&g_xl[(size_t)i * 4] = lv;
    } else {
        int j = i - NX;
        int w = j / NW;
        int off = j % NW;
        const float* s = (w == 0) ? Wq : (w == 1) ? Wk : (w == 2) ? Wv : Wo;
        float4 v = ((const float4*)s)[off];
        uint2 hv = {pack2h(v.x, v.y), pack2h(v.z, v.w)};
        *(uint2*)&g_W[(size_t)w * Dd * Dd + (size_t)off * 4] = hv;
    }
}

// ---------------------------------------------------------------------------
// 2) GEMM (R9 version — validated best): 128x128 block, 8 warps, K-chunk 64,
//    2-stage cp.async, natural MMA order (HW accumulator forwarding).
// ---------------------------------------------------------------------------
constexpr int G_STAGE = 49152;
constexpr int GEMM_SMEM = 2 * G_STAGE;     // 98304 B -> 2 CTAs/SM

template <int MODE>
__global__ __launch_bounds__(256, 2) void gemm_tc(const float* __restrict__ bias,
                                                  float* __restrict__ outd)
{
    extern __shared__ char smc[];
    const uint32_t sb = smaddr(smc);
    const int tid = threadIdx.x, lane = tid & 31, wid = tid >> 5;
    const int wm = wid & 1, wn = wid >> 1;           // warp grid 2m x 4n
    const int m0 = blockIdx.y * 128, n0 = blockIdx.x * 128;
    const int z = (MODE == 0) ? blockIdx.z : 3;

    const __half* pAh = (MODE == 0) ? g_xh : g_ctxh;
    const __half* pAl = (MODE == 0) ? g_xl : g_ctxl;
    const __half* pB  = g_W + (size_t)z * Dd * Dd;

    const int q  = tid & 7;
    const int rs = tid >> 3;

    auto issue = [&](int ch, int st) {
        const int k0 = ch * 64 + q * 8;
        const uint32_t stb = sb + (uint32_t)st * G_STAGE;
#pragma unroll
        for (int j = 0; j < 4; j++) {
            int row = j * 32 + rs;
            uint32_t so = swz(row, q * 16);
            cp16(stb + so,         pAh + (size_t)(m0 + row) * Dd + k0);
            cp16(stb + 16384 + so, pAl + (size_t)(m0 + row) * Dd + k0);
            cp16(stb + 32768 + so, pB  + (size_t)(n0 + row) * Dd + k0);
        }
        CP_COMMIT();
    };

    float acc[4][4][4];
#pragma unroll
    for (int a = 0; a < 4; a++)
#pragma unroll
        for (int b = 0; b < 4; b++)
#pragma unroll
            for (int c = 0; c < 4; c++) acc[a][b][c] = 0.0f;

    issue(0, 0);
    issue(1, 1);

    constexpr int NCH = Dd / 64;   // 16
    for (int ch = 0; ch < NCH; ch++) {
        if (ch < NCH - 1) CP_WAIT1(); else CP_WAIT0();
        __syncthreads();

        const uint32_t aAh = sb + (uint32_t)(ch & 1) * G_STAGE;
        const uint32_t aAl = aAh + 16384;
        const uint32_t aB  = aAh + 32768;

#pragma unroll
        for (int ks = 0; ks < 4; ks++) {
            uint32_t bh[2][4];
            const int g = lane >> 3;
            const int brow = wn * 32 + ((g >> 1) << 3) + (lane & 7);
            const int bqb = ks * 32 + ((g & 1) << 4);
#pragma unroll
            for (int p = 0; p < 2; p++)
                ldsm4(bh[p], aB + swz(brow + p * 16, bqb));

            const int arow = wm * 64 + (lane & 15);
            const int aqb = ks * 32 + ((lane >> 4) << 4);
#pragma unroll
            for (int mt = 0; mt < 4; mt++) {
                uint32_t ah[4], al[4];
                int r = arow + mt * 16;
                ldsm4(ah, aAh + swz(r, aqb));
                ldsm4(al, aAl + swz(r, aqb));
#pragma unroll
                for (int p = 0; p < 2; p++) {
                    mma16816(acc[mt][2 * p],     ah, &bh[p][0]);
                    mma16816(acc[mt][2 * p],     al, &bh[p][0]);
                    mma16816(acc[mt][2 * p + 1], ah, &bh[p][2]);
                    mma16816(acc[mt][2 * p + 1], al, &bh[p][2]);
                }
            }
        }
        __syncthreads();
        if (ch + 2 < NCH) issue(ch + 2, ch & 1);
    }

    // epilogue
    const int g4 = lane >> 2, q2 = (lane & 3) * 2;
    if (MODE == 0) {
#pragma unroll
        for (int mt = 0; mt < 4; mt++)
#pragma unroll
            for (int nt = 0; nt < 4; nt++) {
                int r0 = m0 + wm * 64 + mt * 16 + g4;
                int n  = n0 + wn * 32 + nt * 8 + q2;
                int b = r0 >> 11, s = r0 & 2047;
                int h = n >> 6,  d = n & 63;
                size_t i0 = (((size_t)(b * Hh + h)) * Ss + s) * HD + d;
                size_t i1 = i0 + (size_t)8 * HD;
                if (z == 1) {   // K single fp16
                    *(uint32_t*)&g_Kh[i0] = pack2h(acc[mt][nt][0], acc[mt][nt][1]);
                    *(uint32_t*)&g_Kh[i1] = pack2h(acc[mt][nt][2], acc[mt][nt][3]);
                } else {        // Q or V: 2-term fp16
                    __half* oh = (z == 0) ? g_Qh : g_Vh;
                    __half* ol = (z == 0) ? g_Ql : g_Vl;
                    uint32_t hh, ll;
                    split2h(acc[mt][nt][0], acc[mt][nt][1], hh, ll);
                    *(uint32_t*)&oh[i0] = hh; *(uint32_t*)&ol[i0] = ll;
                    split2h(acc[mt][nt][2], acc[mt][nt][3], hh, ll);
                    *(uint32_t*)&oh[i1] = hh; *(uint32_t*)&ol[i1] = ll;
                }
            }
    } else {
#pragma unroll
        for (int mt = 0; mt < 4; mt++)
#pragma unroll
            for (int nt = 0; nt < 4; nt++) {
                int r0 = m0 + wm * 64 + mt * 16 + g4;
                int n  = n0 + wn * 32 + nt * 8 + q2;
                float b0 = bias[n], b1 = bias[n + 1];
                float2 v0 = {acc[mt][nt][0] + b0, acc[mt][nt][1] + b1};
                float2 v1 = {acc[mt][nt][2] + b0, acc[mt][nt][3] + b1};
                *(float2*)&outd[(size_t)r0 * Dd + n] = v0;
                *(float2*)&outd[(size_t)(r0 + 8) * Dd + n] = v1;
            }
    }
}

// ---------------------------------------------------------------------------
// 3) flash v7: R9 flash (natural MMA order) but 3-stage K/V cp.async with a
//    SINGLE barrier per k-tile (trailing barrier subsumed by next top-sync).
// smem: Qh 16K, Ql 16K, 3 stages x {Kh, Vh, Vl} 8K each = 72K. total 104K.
// ---------------------------------------------------------------------------
constexpr int F_Q   = 16384;
constexpr int F_KV  = 8192;
constexpr int FLASH_SMEM = 2 * F_Q + 9 * F_KV;   // 106496 -> 2 CTAs/SM

__global__ __launch_bounds__(256, 2) void flash_tc()
{
    extern __shared__ char fsc[];
    const uint32_t sb = smaddr(fsc);

    const int tid = threadIdx.x, lane = tid & 31, wid = tid >> 5;
    const int qt = gridDim.x - 1 - blockIdx.x;     // heavy tiles first
    const int bhi = blockIdx.y;
    const size_t base = (size_t)bhi * Ss * HD;
    const float SCL = 0.125f * 1.4426950408889634f;

    const __half* ksrc[3] = {g_Kh + base, g_Vh + base, g_Vl + base};

    const int q  = tid & 7;
    const int rs = tid >> 3;

    auto issue_kv = [&](int kt, int st) {
        const uint32_t stb = sb + 2 * F_Q + (uint32_t)st * 3 * F_KV;
#pragma unroll
        for (int a = 0; a < 3; a++) {
#pragma unroll
            for (int j = 0; j < 2; j++) {
                int row = j * 32 + rs;
                cp16(stb + (uint32_t)a * F_KV + swz(row, q * 16),
                     ksrc[a] + (size_t)(kt * 64 + row) * HD + q * 8);
            }
        }
        CP_COMMIT();
    };

    const int ktmax = 2 * qt + 1;
    issue_kv(0, 0);
    issue_kv(1, 1);

    // Q tile: 128 rows x 64 fp16, hi+lo
#pragma unroll
    for (int j = 0; j < 4; j++) {
        int row = j * 32 + rs;
        size_t go = base + (size_t)(qt * 128 + row) * HD + q * 8;
        *(uint4*)(fsc + swz(row, q * 16))       = *(const uint4*)&g_Qh[go];
        *(uint4*)(fsc + F_Q + swz(row, q * 16)) = *(const uint4*)&g_Ql[go];
    }

    float m0_ = -1e30f, m1_ = -1e30f, l0_ = 0.f, l1_ = 0.f;
    float o[8][4];
#pragma unroll
    for (int t = 0; t < 8; t++)
#pragma unroll
        for (int c = 0; c < 4; c++) o[t][c] = 0.f;

    const uint32_t aQh = sb, aQl = sb + F_Q;

    for (int kt = 0; kt <= ktmax; kt++) {
        if (kt < ktmax) CP_WAIT1(); else CP_WAIT0();
        __syncthreads();   // also proves compute(kt-1) done -> stage reuse safe
        if (kt + 2 <= ktmax) issue_kv(kt + 2, (kt + 2) % 3);

        const uint32_t stb = sb + 2 * F_Q + (uint32_t)(kt % 3) * 3 * F_KV;
        const uint32_t aK  = stb;
        const uint32_t aVh = stb + F_KV, aVl = stb + 2 * F_KV;

        // S = Q K^T (2-term, natural order — HW acc forwarding)
        float s[8][4];
#pragma unroll
        for (int t = 0; t < 8; t++)
#pragma unroll
            for (int c = 0; c < 4; c++) s[t][c] = 0.f;

#pragma unroll
        for (int ks = 0; ks < 4; ks++) {
            uint32_t qh[4], ql[4];
            const int arow = wid * 16 + (lane & 15);
            const int aqb  = ks * 32 + ((lane >> 4) << 4);
            ldsm4(qh, aQh + swz(arow, aqb));
            ldsm4(ql, aQl + swz(arow, aqb));
            const int g = lane >> 3;
            const int br = ((g >> 1) << 3) + (lane & 7);
            const int bqb = ks * 32 + ((g & 1) << 4);
#pragma unroll
            for (int p = 0; p < 4; p++) {
                uint32_t kh[4];
                ldsm4(kh, aK + swz(br + p * 16, bqb));
                mma16816(s[2 * p],     qh, &kh[0]);
                mma16816(s[2 * p],     ql, &kh[0]);
                mma16816(s[2 * p + 1], qh, &kh[2]);
                mma16816(s[2 * p + 1], ql, &kh[2]);
            }
        }

        // scale (base-2) + causal mask (last two k-tiles only)
        const int r0g = qt * 128 + wid * 16 + (lane >> 2);
        const int r1g = r0g + 8;
        const bool needmask = (kt >= 2 * qt);
        float mx0 = -1e30f, mx1 = -1e30f;
#pragma unroll
        for (int t = 0; t < 8; t++) {
            int cg = kt * 64 + t * 8 + (lane & 3) * 2;
            float v0 = s[t][0] * SCL, v1 = s[t][1] * SCL;
            float v2 = s[t][2] * SCL, v3 = s[t][3] * SCL;
            if (needmask) {
                if (cg     > r0g) v0 = -1e30f;
                if (cg + 1 > r0g) v1 = -1e30f;
                if (cg     > r1g) v2 = -1e30f;
                if (cg + 1 > r1g) v3 = -1e30f;
            }
            s[t][0] = v0; s[t][1] = v1; s[t][2] = v2; s[t][3] = v3;
            mx0 = fmaxf(mx0, fmaxf(v0, v1));
            mx1 = fmaxf(mx1, fmaxf(v2, v3));
        }
        mx0 = fmaxf(mx0, __shfl_xor_sync(0xffffffffu, mx0, 1));
        mx0 = fmaxf(mx0, __shfl_xor_sync(0xffffffffu, mx0, 2));
        mx1 = fmaxf(mx1, __shfl_xor_sync(0xffffffffu, mx1, 1));
        mx1 = fmaxf(mx1, __shfl_xor_sync(0xffffffffu, mx1, 2));
        float nm0 = fmaxf(m0_, mx0), nm1 = fmaxf(m1_, mx1);
        float al0 = ex2f(m0_ - nm0), al1 = ex2f(m1_ - nm1);
        float sum0 = 0.f, sum1 = 0.f;
#pragma unroll
        for (int t = 0; t < 8; t++) {
            float p0 = ex2f(s[t][0] - nm0), p1 = ex2f(s[t][1] - nm0);
            float p2 = ex2f(s[t][2] - nm1), p3 = ex2f(s[t][3] - nm1);
            s[t][0] = p0; s[t][1] = p1; s[t][2] = p2; s[t][3] = p3;
            sum0 += p0 + p1; sum1 += p2 + p3;
        }
        sum0 += __shfl_xor_sync(0xffffffffu, sum0, 1);
        sum0 += __shfl_xor_sync(0xffffffffu, sum0, 2);
        sum1 += __shfl_xor_sync(0xffffffffu, sum1, 1);
        sum1 += __shfl_xor_sync(0xffffffffu, sum1, 2);
        l0_ = l0_ * al0 + sum0;
        l1_ = l1_ * al1 + sum1;
        m0_ = nm0; m1_ = nm1;
#pragma unroll
        for (int t = 0; t < 8; t++) {
            o[t][0] *= al0; o[t][1] *= al0;
            o[t][2] *= al1; o[t][3] *= al1;
        }

        // pack P (single fp16) into A-fragments
        uint32_t pa[4][4];
#pragma unroll
        for (int t = 0; t < 4; t++) {
            pa[t][0] = pack2h(s[2 * t][0],     s[2 * t][1]);
            pa[t][1] = pack2h(s[2 * t][2],     s[2 * t][3]);
            pa[t][2] = pack2h(s[2 * t + 1][0], s[2 * t + 1][1]);
            pa[t][3] = pack2h(s[2 * t + 1][2], s[2 * t + 1][3]);
        }

        // O += P V (2-term, natural order), V via ldmatrix.trans
        const int g = lane >> 3;
        const int vr = ((g & 1) << 3) + (lane & 7);
        const int vcb = (lane >= 16) ? 16 : 0;
#pragma unroll
        for (int t = 0; t < 4; t++) {
            int r = t * 16 + vr;
#pragma unroll
            for (int dp = 0; dp < 4; dp++) {
                uint32_t vh[4], vl[4];
                int b = dp * 32 + vcb;
                ldsm4t(vh, aVh + swz(r, b));
                ldsm4t(vl, aVl + swz(r, b));
                mma16816(o[2 * dp],     pa[t], &vh[0]);
                mma16816(o[2 * dp],     pa[t], &vl[0]);
                mma16816(o[2 * dp + 1], pa[t], &vh[2]);
                mma16816(o[2 * dp + 1], pa[t], &vl[2]);
            }
        }
        // no trailing barrier: next iteration's top __syncthreads covers reuse
    }

    // epilogue: normalize, 2-term fp16 ctx [B*S, D]
    const int b = bhi >> 4, h = bhi & 15;
    const float i0 = 1.f / l0_, i1 = 1.f / l1_;
    const int r0 = qt * 128 + wid * 16 + (lane >> 2);
    const size_t row0 = (size_t)(b * Ss + r0) * Dd;
    const size_t row1 = row0 + (size_t)8 * Dd;
#pragma unroll
    for (int dt = 0; dt < 8; dt++) {
        int d = h * 64 + dt * 8 + (lane & 3) * 2;
        uint32_t hh, ll;
        split2h(o[dt][0] * i0, o[dt][1] * i0, hh, ll);
        *(uint32_t*)&g_ctxh[row0 + d] = hh;
        *(uint32_t*)&g_ctxl[row0 + d] = ll;
        split2h(o[dt][2] * i1, o[dt][3] * i1, hh, ll);
        *(uint32_t*)&g_ctxh[row1 + d] = hh;
        *(uint32_t*)&g_ctxl[row1 + d] = ll;
    }
}

// ---------------------------------------------------------------------------
extern "C" void kernel_launch(void* const* d_in, const int* in_sizes, int n_in,
                              void* d_out, int out_size)
{
    const float* x  = (const float*)d_in[0];
    const float* Wq = (const float*)d_in[1];
    const float* Wk = (const float*)d_in[2];
    const float* Wv = (const float*)d_in[3];
    const float* Wo = (const float*)d_in[4];
    const float* bo = (const float*)d_in[5];
    float* out = (float*)d_out;

    cudaFuncSetAttribute(gemm_tc<0>, cudaFuncAttributeMaxDynamicSharedMemorySize,
                         GEMM_SMEM);
    cudaFuncSetAttribute(gemm_tc<1>, cudaFuncAttributeMaxDynamicSharedMemorySize,
                         GEMM_SMEM);
    cudaFuncSetAttribute(flash_tc, cudaFuncAttributeMaxDynamicSharedMemorySize,
                         FLASH_SMEM);

    convert_split<<<(Mm * Dd / 4 + 4 * Dd * Dd / 4 + 255) / 256, 256>>>(
        x, Wq, Wk, Wv, Wo);

    gemm_tc<0><<<dim3(Dd / 128, Mm / 128, 3), 256, GEMM_SMEM>>>(nullptr, nullptr);

    flash_tc<<<dim3(Ss / 128, Bb * Hh), 256, FLASH_SMEM>>>();

    gemm_tc<1><<<dim3(Dd / 128, Mm / 128, 1), 256, GEMM_SMEM>>>(bo, out);
}

// round 12
// speedup vs baseline: 1.9059x; 1.2431x over previous
#include <cuda_runtime.h>
#include <cuda_fp16.h>
#include <cstdint>

constexpr int Bb = 2, Ss = 2048, Dd = 1024, Hh = 16, HD = 64;
constexpr int Mm = Bb * Ss;  // 4096

// fp16 scratch (allocation-free rule: __device__ globals)
__device__ __align__(256) __half g_xh[Mm * Dd],  g_xl[Mm * Dd];   // x 2-term
__device__ __align__(256) __half g_W[4 * Dd * Dd];                // W single (q,k,v,o)
__device__ __align__(256) __half g_Qh[Mm * Dd],  g_Ql[Mm * Dd];   // Q 2-term [B,H,S,HD]
__device__ __align__(256) __half g_Kh[Mm * Dd];                   // K single
__device__ __align__(256) __half g_Vh[Mm * Dd];                   // V single
__device__ __align__(256) __half g_ctx[Mm * Dd];                  // ctx single [B*S,D]

// ---------------------------------------------------------------------------
// helpers
// ---------------------------------------------------------------------------
__device__ __forceinline__ uint32_t smaddr(const void* p) {
    uint32_t a;
    asm("{ .reg .u64 t; cvta.to.shared.u64 t, %1; cvt.u32.u64 %0, t; }"
        : "=r"(a) : "l"(p));
    return a;
}
// SW128 swizzle for 128B rows
__device__ __forceinline__ uint32_t swz(int r, int b) {
    return (uint32_t)(r * 128 + (b ^ ((r & 7) << 4)));
}
__device__ __forceinline__ void ldsm4(uint32_t* r, uint32_t a) {
    asm volatile("ldmatrix.sync.aligned.m8n8.x4.shared.b16 {%0,%1,%2,%3}, [%4];"
                 : "=r"(r[0]), "=r"(r[1]), "=r"(r[2]), "=r"(r[3]) : "r"(a));
}
__device__ __forceinline__ void ldsm4t(uint32_t* r, uint32_t a) {
    asm volatile("ldmatrix.sync.aligned.m8n8.x4.trans.shared.b16 {%0,%1,%2,%3}, [%4];"
                 : "=r"(r[0]), "=r"(r[1]), "=r"(r[2]), "=r"(r[3]) : "r"(a));
}
__device__ __forceinline__ void mma16816(float* c, const uint32_t* a, const uint32_t* b) {
    asm volatile(
        "mma.sync.aligned.m16n8k16.row.col.f32.f16.f16.f32 "
        "{%0,%1,%2,%3}, {%4,%5,%6,%7}, {%8,%9}, {%0,%1,%2,%3};"
        : "+f"(c[0]), "+f"(c[1]), "+f"(c[2]), "+f"(c[3])
        : "r"(a[0]), "r"(a[1]), "r"(a[2]), "r"(a[3]), "r"(b[0]), "r"(b[1]));
}
__device__ __forceinline__ float ex2f(float x) {
    float y;
    asm("ex2.approx.ftz.f32 %0, %1;" : "=f"(y) : "f"(x));
    return y;
}
__device__ __forceinline__ void cp16(uint32_t dst, const void* src) {
    asm volatile("cp.async.cg.shared.global [%0], [%1], 16;" :: "r"(dst), "l"(src));
}
#define CP_COMMIT() asm volatile("cp.async.commit_group;" ::: "memory")
#define CP_WAIT1()  asm volatile("cp.async.wait_group 1;" ::: "memory")
#define CP_WAIT0()  asm volatile("cp.async.wait_group 0;" ::: "memory")

__device__ __forceinline__ uint32_t pack2h(float a, float b) {
    __half2 v = __floats2half2_rn(a, b);
    return *reinterpret_cast<uint32_t*>(&v);
}
__device__ __forceinline__ void split2h(float a, float b, uint32_t& h, uint32_t& l) {
    __half2 hv = __floats2half2_rn(a, b);
    float2 hf = __half22float2(hv);
    __half2 lv = __floats2half2_rn(a - hf.x, b - hf.y);
    h = *reinterpret_cast<uint32_t*>(&hv);
    l = *reinterpret_cast<uint32_t*>(&lv);
}

// ---------------------------------------------------------------------------
// 1) convert: x -> fp16 2-term; W -> fp16 single
// ---------------------------------------------------------------------------
__global__ __launch_bounds__(256) void convert_split(const float* __restrict__ x,
                                                     const float* __restrict__ Wq,
                                                     const float* __restrict__ Wk,
                                                     const float* __restrict__ Wv,
                                                     const float* __restrict__ Wo)
{
    const int NX = Mm * Dd / 4;
    const int NW = Dd * Dd / 4;
    int i = blockIdx.x * 256 + threadIdx.x;
    if (i >= NX + 4 * NW) return;

    if (i < NX) {
        float4 v = ((const float4*)x)[i];
        uint32_t h01, l01, h23, l23;
        split2h(v.x, v.y, h01, l01);
        split2h(v.z, v.w, h23, l23);
        uint2 hv = {h01, h23}, lv = {l01, l23};
        *(uint2*)&g_xh[(size_t)i * 4] = hv;
        *(uint2*)&g_xl[(size_t)i * 4] = lv;
    } else {
        int j = i - NX;
        int w = j / NW;
        int off = j % NW;
        const float* s = (w == 0) ? Wq : (w == 1) ? Wk : (w == 2) ? Wv : Wo;
        float4 v = ((const float4*)s)[off];
        uint2 hv = {pack2h(v.x, v.y), pack2h(v.z, v.w)};
        *(uint2*)&g_W[(size_t)w * Dd * Dd + (size_t)off * 4] = hv;
    }
}

// ---------------------------------------------------------------------------
// 2) GEMM: 128x128 block, 8 warps (64x32 warp tile), K-chunk 64, 2-stage
//    cp.async, natural MMA order. Stage layout: Ah 16K | Al 16K | B 16K.
// MODE 0: A = x 2-term; z=0 -> Wq -> Q 2-term out; z=1 -> Wv -> V single out
// MODE 2: A = x single (hi);       Wk -> K single out
// MODE 1: A = ctx single;          Wo -> fp32 out + bias
// ---------------------------------------------------------------------------
constexpr int G_STAGE = 49152;
constexpr int GEMM_SMEM = 2 * G_STAGE;     // 98304 B -> 2 CTAs/SM

template <int MODE>
__global__ __launch_bounds__(256, 2) void gemm_tc(const float* __restrict__ bias,
                                                  float* __restrict__ outd)
{
    extern __shared__ char smc[];
    const uint32_t sb = smaddr(smc);
    const int tid = threadIdx.x, lane = tid & 31, wid = tid >> 5;
    const int wm = wid & 1, wn = wid >> 1;           // warp grid 2m x 4n
    const int m0 = blockIdx.y * 128, n0 = blockIdx.x * 128;
    const int z = (MODE == 0) ? blockIdx.z : 0;
    constexpr bool A2 = (MODE == 0);                 // 2-term A?

    const __half* pAh = (MODE == 1) ? g_ctx : g_xh;
    const __half* pAl = g_xl;
    const int widx = (MODE == 0) ? (z == 0 ? 0 : 2) : (MODE == 2 ? 1 : 3);
    const __half* pB  = g_W + (size_t)widx * Dd * Dd;

    const int q  = tid & 7;
    const int rs = tid >> 3;

    auto issue = [&](int ch, int st) {
        const int k0 = ch * 64 + q * 8;
        const uint32_t stb = sb + (uint32_t)st * G_STAGE;
#pragma unroll
        for (int j = 0; j < 4; j++) {
            int row = j * 32 + rs;
            uint32_t so = swz(row, q * 16);
            cp16(stb + so, pAh + (size_t)(m0 + row) * Dd + k0);
            if (A2)
                cp16(stb + 16384 + so, pAl + (size_t)(m0 + row) * Dd + k0);
            cp16(stb + 32768 + so, pB + (size_t)(n0 + row) * Dd + k0);
        }
        CP_COMMIT();
    };

    float acc[4][4][4];
#pragma unroll
    for (int a = 0; a < 4; a++)
#pragma unroll
        for (int b = 0; b < 4; b++)
#pragma unroll
            for (int c = 0; c < 4; c++) acc[a][b][c] = 0.0f;

    issue(0, 0);
    issue(1, 1);

    constexpr int NCH = Dd / 64;   // 16
    for (int ch = 0; ch < NCH; ch++) {
        if (ch < NCH - 1) CP_WAIT1(); else CP_WAIT0();
        __syncthreads();

        const uint32_t aAh = sb + (uint32_t)(ch & 1) * G_STAGE;
        const uint32_t aAl = aAh + 16384;
        const uint32_t aB  = aAh + 32768;

#pragma unroll
        for (int ks = 0; ks < 4; ks++) {
            uint32_t bh[2][4];
            const int g = lane >> 3;
            const int brow = wn * 32 + ((g >> 1) << 3) + (lane & 7);
            const int bqb = ks * 32 + ((g & 1) << 4);
#pragma unroll
            for (int p = 0; p < 2; p++)
                ldsm4(bh[p], aB + swz(brow + p * 16, bqb));

            const int arow = wm * 64 + (lane & 15);
            const int aqb = ks * 32 + ((lane >> 4) << 4);
#pragma unroll
            for (int mt = 0; mt < 4; mt++) {
                int r = arow + mt * 16;
                uint32_t ah[4];
                ldsm4(ah, aAh + swz(r, aqb));
                if (A2) {
                    uint32_t al[4];
                    ldsm4(al, aAl + swz(r, aqb));
#pragma unroll
                    for (int p = 0; p < 2; p++) {
                        mma16816(acc[mt][2 * p],     ah, &bh[p][0]);
                        mma16816(acc[mt][2 * p],     al, &bh[p][0]);
                        mma16816(acc[mt][2 * p + 1], ah, &bh[p][2]);
                        mma16816(acc[mt][2 * p + 1], al, &bh[p][2]);
                    }
                } else {
#pragma unroll
                    for (int p = 0; p < 2; p++) {
                        mma16816(acc[mt][2 * p],     ah, &bh[p][0]);
                        mma16816(acc[mt][2 * p + 1], ah, &bh[p][2]);
                    }
                }
            }
        }
        __syncthreads();
        if (ch + 2 < NCH) issue(ch + 2, ch & 1);
    }

    // epilogue
    const int g4 = lane >> 2, q2 = (lane & 3) * 2;
#pragma unroll
    for (int mt = 0; mt < 4; mt++)
#pragma unroll
        for (int nt = 0; nt < 4; nt++) {
            int r0 = m0 + wm * 64 + mt * 16 + g4;
            int n  = n0 + wn * 32 + nt * 8 + q2;
            if (MODE == 1) {
                float b0 = bias[n], b1 = bias[n + 1];
                float2 v0 = {acc[mt][nt][0] + b0, acc[mt][nt][1] + b1};
                float2 v1 = {acc[mt][nt][2] + b0, acc[mt][nt][3] + b1};
                *(float2*)&outd[(size_t)r0 * Dd + n] = v0;
                *(float2*)&outd[(size_t)(r0 + 8) * Dd + n] = v1;
            } else {
                int b = r0 >> 11, s = r0 & 2047;
                int h = n >> 6,  d = n & 63;
                size_t i0 = (((size_t)(b * Hh + h)) * Ss + s) * HD + d;
                size_t i1 = i0 + (size_t)8 * HD;
                if (MODE == 2) {            // K single
                    *(uint32_t*)&g_Kh[i0] = pack2h(acc[mt][nt][0], acc[mt][nt][1]);
                    *(uint32_t*)&g_Kh[i1] = pack2h(acc[mt][nt][2], acc[mt][nt][3]);
                } else if (z == 1) {        // V single
                    *(uint32_t*)&g_Vh[i0] = pack2h(acc[mt][nt][0], acc[mt][nt][1]);
                    *(uint32_t*)&g_Vh[i1] = pack2h(acc[mt][nt][2], acc[mt][nt][3]);
                } else {                    // Q 2-term
                    uint32_t hh, ll;
                    split2h(acc[mt][nt][0], acc[mt][nt][1], hh, ll);
                    *(uint32_t*)&g_Qh[i0] = hh; *(uint32_t*)&g_Ql[i0] = ll;
                    split2h(acc[mt][nt][2], acc[mt][nt][3], hh, ll);
                    *(uint32_t*)&g_Qh[i1] = hh; *(uint32_t*)&g_Ql[i1] = ll;
                }
            }
        }
}

// ---------------------------------------------------------------------------
// 3) flash: q-tile 128 (256 thr, 8 warps), k-tile 64. Q 2-term; K, V single.
//    3-stage cp.async K/V, single barrier per k-tile. ctx single out.
// smem: Qh 16K, Ql 16K, 3 stages x {K, V} 8K each = 48K. total 80K.
// ---------------------------------------------------------------------------
constexpr int F_Q   = 16384;
constexpr int F_KV  = 8192;
constexpr int FLASH_SMEM = 2 * F_Q + 6 * F_KV;   // 81920 -> 2 CTAs/SM

__global__ __launch_bounds__(256, 2) void flash_tc()
{
    extern __shared__ char fsc[];
    const uint32_t sb = smaddr(fsc);

    const int tid = threadIdx.x, lane = tid & 31, wid = tid >> 5;
    const int qt = gridDim.x - 1 - blockIdx.x;     // heavy tiles first
    const int bhi = blockIdx.y;
    const size_t base = (size_t)bhi * Ss * HD;
    const float SCL = 0.125f * 1.4426950408889634f;

    const __half* ksrc[2] = {g_Kh + base, g_Vh + base};

    const int q  = tid & 7;
    const int rs = tid >> 3;

    auto issue_kv = [&](int kt, int st) {
        const uint32_t stb = sb + 2 * F_Q + (uint32_t)st * 2 * F_KV;
#pragma unroll
        for (int a = 0; a < 2; a++) {
#pragma unroll
            for (int j = 0; j < 2; j++) {
                int row = j * 32 + rs;
                cp16(stb + (uint32_t)a * F_KV + swz(row, q * 16),
                     ksrc[a] + (size_t)(kt * 64 + row) * HD + q * 8);
            }
        }
        CP_COMMIT();
    };

    const int ktmax = 2 * qt + 1;
    issue_kv(0, 0);
    issue_kv(1, 1);

    // Q tile: 128 rows x 64 fp16, hi+lo
#pragma unroll
    for (int j = 0; j < 4; j++) {
        int row = j * 32 + rs;
        size_t go = base + (size_t)(qt * 128 + row) * HD + q * 8;
        *(uint4*)(fsc + swz(row, q * 16))       = *(const uint4*)&g_Qh[go];
        *(uint4*)(fsc + F_Q + swz(row, q * 16)) = *(const uint4*)&g_Ql[go];
    }

    float m0_ = -1e30f, m1_ = -1e30f, l0_ = 0.f, l1_ = 0.f;
    float o[8][4];
#pragma unroll
    for (int t = 0; t < 8; t++)
#pragma unroll
        for (int c = 0; c < 4; c++) o[t][c] = 0.f;

    const uint32_t aQh = sb, aQl = sb + F_Q;

    for (int kt = 0; kt <= ktmax; kt++) {
        if (kt < ktmax) CP_WAIT1(); else CP_WAIT0();
        __syncthreads();   // also proves compute(kt-1) done -> stage reuse safe
        if (kt + 2 <= ktmax) issue_kv(kt + 2, (kt + 2) % 3);

        const uint32_t stb = sb + 2 * F_Q + (uint32_t)(kt % 3) * 2 * F_KV;
        const uint32_t aK = stb, aV = stb + F_KV;

        // S = Q K^T (Q 2-term, K single)
        float s[8][4];
#pragma unroll
        for (int t = 0; t < 8; t++)
#pragma unroll
            for (int c = 0; c < 4; c++) s[t][c] = 0.f;

#pragma unroll
        for (int ks = 0; ks < 4; ks++) {
            uint32_t qh[4], ql[4];
            const int arow = wid * 16 + (lane & 15);
            const int aqb  = ks * 32 + ((lane >> 4) << 4);
            ldsm4(qh, aQh + swz(arow, aqb));
            ldsm4(ql, aQl + swz(arow, aqb));
            const int g = lane >> 3;
            const int br = ((g >> 1) << 3) + (lane & 7);
            const int bqb = ks * 32 + ((g & 1) << 4);
#pragma unroll
            for (int p = 0; p < 4; p++) {
                uint32_t kh[4];
                ldsm4(kh, aK + swz(br + p * 16, bqb));
                mma16816(s[2 * p],     qh, &kh[0]);
                mma16816(s[2 * p],     ql, &kh[0]);
                mma16816(s[2 * p + 1], qh, &kh[2]);
                mma16816(s[2 * p + 1], ql, &kh[2]);
            }
        }

        // scale (base-2) + causal mask (last two k-tiles only)
        const int r0g = qt * 128 + wid * 16 + (lane >> 2);
        const int r1g = r0g + 8;
        const bool needmask = (kt >= 2 * qt);
        float mx0 = -1e30f, mx1 = -1e30f;
#pragma unroll
        for (int t = 0; t < 8; t++) {
            int cg = kt * 64 + t * 8 + (lane & 3) * 2;
            float v0 = s[t][0] * SCL, v1 = s[t][1] * SCL;
            float v2 = s[t][2] * SCL, v3 = s[t][3] * SCL;
            if (needmask) {
                if (cg     > r0g) v0 = -1e30f;
                if (cg + 1 > r0g) v1 = -1e30f;
                if (cg     > r1g) v2 = -1e30f;
                if (cg + 1 > r1g) v3 = -1e30f;
            }
            s[t][0] = v0; s[t][1] = v1; s[t][2] = v2; s[t][3] = v3;
            mx0 = fmaxf(mx0, fmaxf(v0, v1));
            mx1 = fmaxf(mx1, fmaxf(v2, v3));
        }
        mx0 = fmaxf(mx0, __shfl_xor_sync(0xffffffffu, mx0, 1));
        mx0 = fmaxf(mx0, __shfl_xor_sync(0xffffffffu, mx0, 2));
        mx1 = fmaxf(mx1, __shfl_xor_sync(0xffffffffu, mx1, 1));
        mx1 = fmaxf(mx1, __shfl_xor_sync(0xffffffffu, mx1, 2));
        float nm0 = fmaxf(m0_, mx0), nm1 = fmaxf(m1_, mx1);
        float al0 = ex2f(m0_ - nm0), al1 = ex2f(m1_ - nm1);
        float sum0 = 0.f, sum1 = 0.f;
#pragma unroll
        for (int t = 0; t < 8; t++) {
            float p0 = ex2f(s[t][0] - nm0), p1 = ex2f(s[t][1] - nm0);
            float p2 = ex2f(s[t][2] - nm1), p3 = ex2f(s[t][3] - nm1);
            s[t][0] = p0; s[t][1] = p1; s[t][2] = p2; s[t][3] = p3;
            sum0 += p0 + p1; sum1 += p2 + p3;
        }
        sum0 += __shfl_xor_sync(0xffffffffu, sum0, 1);
        sum0 += __shfl_xor_sync(0xffffffffu, sum0, 2);
        sum1 += __shfl_xor_sync(0xffffffffu, sum1, 1);
        sum1 += __shfl_xor_sync(0xffffffffu, sum1, 2);
        l0_ = l0_ * al0 + sum0;
        l1_ = l1_ * al1 + sum1;
        m0_ = nm0; m1_ = nm1;
#pragma unroll
        for (int t = 0; t < 8; t++) {
            o[t][0] *= al0; o[t][1] *= al0;
            o[t][2] *= al1; o[t][3] *= al1;
        }

        // pack P (single fp16) into A-fragments
        uint32_t pa[4][4];
#pragma unroll
        for (int t = 0; t < 4; t++) {
            pa[t][0] = pack2h(s[2 * t][0],     s[2 * t][1]);
            pa[t][1] = pack2h(s[2 * t][2],     s[2 * t][3]);
            pa[t][2] = pack2h(s[2 * t + 1][0], s[2 * t + 1][1]);
            pa[t][3] = pack2h(s[2 * t + 1][2], s[2 * t + 1][3]);
        }

        // O += P V (V single), V via ldmatrix.trans
        const int g = lane >> 3;
        const int vr = ((g & 1) << 3) + (lane & 7);
        const int vcb = (lane >= 16) ? 16 : 0;
#pragma unroll
        for (int t = 0; t < 4; t++) {
            int r = t * 16 + vr;
#pragma unroll
            for (int dp = 0; dp < 4; dp++) {
                uint32_t vh[4];
                ldsm4t(vh, aV + swz(r, dp * 32 + vcb));
                mma16816(o[2 * dp],     pa[t], &vh[0]);
                mma16816(o[2 * dp + 1], pa[t], &vh[2]);
            }
        }
        // no trailing barrier: next iteration's top __syncthreads covers reuse
    }

    // epilogue: normalize, single fp16 ctx [B*S, D]
    const int b = bhi >> 4, h = bhi & 15;
    const float i0 = 1.f / l0_, i1 = 1.f / l1_;
    const int r0 = qt * 128 + wid * 16 + (lane >> 2);
    const size_t row0 = (size_t)(b * Ss + r0) * Dd;
    const size_t row1 = row0 + (size_t)8 * Dd;
#pragma unroll
    for (int dt = 0; dt < 8; dt++) {
        int d = h * 64 + dt * 8 + (lane & 3) * 2;
        *(uint32_t*)&g_ctx[row0 + d] = pack2h(o[dt][0] * i0, o[dt][1] * i0);
        *(uint32_t*)&g_ctx[row1 + d] = pack2h(o[dt][2] * i1, o[dt][3] * i1);
    }
}

// ---------------------------------------------------------------------------
extern "C" void kernel_launch(void* const* d_in, const int* in_sizes, int n_in,
                              void* d_out, int out_size)
{
    const float* x  = (const float*)d_in[0];
    const float* Wq = (const float*)d_in[1];
    const float* Wk = (const float*)d_in[2];
    const float* Wv = (const float*)d_in[3];
    const float* Wo = (const float*)d_in[4];
    const float* bo = (const float*)d_in[5];
    float* out = (float*)d_out;

    cudaFuncSetAttribute(gemm_tc<0>, cudaFuncAttributeMaxDynamicSharedMemorySize,
                         GEMM_SMEM);
    cudaFuncSetAttribute(gemm_tc<1>, cudaFuncAttributeMaxDynamicSharedMemorySize,
                         GEMM_SMEM);
    cudaFuncSetAttribute(gemm_tc<2>, cudaFuncAttributeMaxDynamicSharedMemorySize,
                         GEMM_SMEM);
    cudaFuncSetAttribute(flash_tc, cudaFuncAttributeMaxDynamicSharedMemorySize,
                         FLASH_SMEM);

    // 1) x -> fp16 2-term; W -> fp16 single
    convert_split<<<(Mm * Dd / 4 + 4 * Dd * Dd / 4 + 255) / 256, 256>>>(
        x, Wq, Wk, Wv, Wo);

    // 2) projections: Q (2-term out) + V (single out) share MODE 0; K is MODE 2
    gemm_tc<0><<<dim3(Dd / 128, Mm / 128, 2), 256, GEMM_SMEM>>>(nullptr, nullptr);
    gemm_tc<2><<<dim3(Dd / 128, Mm / 128, 1), 256, GEMM_SMEM>>>(nullptr, nullptr);

    // 3) causal flash attention (q-tile 128, heavy-first)
    flash_tc<<<dim3(Ss / 128, Bb * Hh), 256, FLASH_SMEM>>>();

    // 4) output projection + bias (single-A)
    gemm_tc<1><<<dim3(Dd / 128, Mm / 128, 1), 256, GEMM_SMEM>>>(bo, out);
}

// round 13
// speedup vs baseline: 2.5383x; 1.3318x over previous
#include <cuda_runtime.h>
#include <cuda_fp16.h>
#include <cstdint>

constexpr int Bb = 2, Ss = 2048, Dd = 1024, Hh = 16, HD = 64;
constexpr int Mm = Bb * Ss;  // 4096

// fp16 scratch (allocation-free rule: __device__ globals) — all single fp16
__device__ __align__(256) __half g_x[Mm * Dd];
__device__ __align__(256) __half g_W[4 * Dd * Dd];        // Wq, Wk, Wv, Wo
__device__ __align__(256) __half g_Q[Mm * Dd];            // [B,H,S,HD]
__device__ __align__(256) __half g_K[Mm * Dd];
__device__ __align__(256) __half g_V[Mm * Dd];
__device__ __align__(256) __half g_ctx[Mm * Dd];          // [B*S, D]

// ---------------------------------------------------------------------------
// helpers
// ---------------------------------------------------------------------------
__device__ __forceinline__ uint32_t smaddr(const void* p) {
    uint32_t a;
    asm("{ .reg .u64 t; cvta.to.shared.u64 t, %1; cvt.u32.u64 %0, t; }"
        : "=r"(a) : "l"(p));
    return a;
}
__device__ __forceinline__ uint32_t swz(int r, int b) {
    return (uint32_t)(r * 128 + (b ^ ((r & 7) << 4)));
}
__device__ __forceinline__ void ldsm4(uint32_t* r, uint32_t a) {
    asm volatile("ldmatrix.sync.aligned.m8n8.x4.shared.b16 {%0,%1,%2,%3}, [%4];"
                 : "=r"(r[0]), "=r"(r[1]), "=r"(r[2]), "=r"(r[3]) : "r"(a));
}
__device__ __forceinline__ void ldsm4t(uint32_t* r, uint32_t a) {
    asm volatile("ldmatrix.sync.aligned.m8n8.x4.trans.shared.b16 {%0,%1,%2,%3}, [%4];"
                 : "=r"(r[0]), "=r"(r[1]), "=r"(r[2]), "=r"(r[3]) : "r"(a));
}
__device__ __forceinline__ void mma16816(float* c, const uint32_t* a, const uint32_t* b) {
    asm volatile(
        "mma.sync.aligned.m16n8k16.row.col.f32.f16.f16.f32 "
        "{%0,%1,%2,%3}, {%4,%5,%6,%7}, {%8,%9}, {%0,%1,%2,%3};"
        : "+f"(c[0]), "+f"(c[1]), "+f"(c[2]), "+f"(c[3])
        : "r"(a[0]), "r"(a[1]), "r"(a[2]), "r"(a[3]), "r"(b[0]), "r"(b[1]));
}
__device__ __forceinline__ float ex2f(float x) {
    float y;
    asm("ex2.approx.ftz.f32 %0, %1;" : "=f"(y) : "f"(x));
    return y;
}
__device__ __forceinline__ void cp16(uint32_t dst, const void* src) {
    asm volatile("cp.async.cg.shared.global [%0], [%1], 16;" :: "r"(dst), "l"(src));
}
#define CP_COMMIT() asm volatile("cp.async.commit_group;" ::: "memory")
#define CP_WAIT1()  asm volatile("cp.async.wait_group 1;" ::: "memory")
#define CP_WAIT0()  asm volatile("cp.async.wait_group 0;" ::: "memory")

__device__ __forceinline__ uint32_t pack2h(float a, float b) {
    __half2 v = __floats2half2_rn(a, b);
    return *reinterpret_cast<uint32_t*>(&v);
}

// ---------------------------------------------------------------------------
// 1) convert: x and W -> single fp16
// ---------------------------------------------------------------------------
__global__ __launch_bounds__(256) void convert_fp16(const float* __restrict__ x,
                                                    const float* __restrict__ Wq,
                                                    const float* __restrict__ Wk,
                                                    const float* __restrict__ Wv,
                                                    const float* __restrict__ Wo)
{
    const int NX = Mm * Dd / 4;
    const int NW = Dd * Dd / 4;
    int i = blockIdx.x * 256 + threadIdx.x;
    if (i >= NX + 4 * NW) return;

    const float4* src;
    __half* dst;
    int off;
    if (i < NX) {
        src = (const float4*)x; dst = g_x; off = i;
    } else {
        int j = i - NX;
        int w = j / NW;
        off = j % NW;
        const float* s = (w == 0) ? Wq : (w == 1) ? Wk : (w == 2) ? Wv : Wo;
        src = (const float4*)s;
        dst = g_W + (size_t)w * Dd * Dd;
    }
    float4 v = src[off];
    uint2 hv = {pack2h(v.x, v.y), pack2h(v.z, v.w)};
    *(uint2*)&dst[(size_t)off * 4] = hv;
}

// ---------------------------------------------------------------------------
// 2) GEMM: 128x128 block, 8 warps (64x32 warp tile), K-chunk 64, single fp16,
//    3-stage cp.async with ONE barrier per chunk, 2 CTAs/SM.
//    Stage (32KB): A 16K | B 16K.
// MODE 0: A = x; z selects Wq/Wk/Wv -> Q/K/V single out [B,H,S,HD]
// MODE 1: A = ctx; Wo -> fp32 out + bias
// ---------------------------------------------------------------------------
constexpr int G_STAGE = 32768;
constexpr int GEMM_SMEM = 3 * G_STAGE;     // 98304 B -> 2 CTAs/SM

template <int MODE>
__global__ __launch_bounds__(256, 2) void gemm_tc(const float* __restrict__ bias,
                                                  float* __restrict__ outd)
{
    extern __shared__ char smc[];
    const uint32_t sb = smaddr(smc);
    const int tid = threadIdx.x, lane = tid & 31, wid = tid >> 5;
    const int wm = wid & 1, wn = wid >> 1;           // warp grid 2m x 4n
    const int m0 = blockIdx.y * 128, n0 = blockIdx.x * 128;
    const int z = (MODE == 0) ? blockIdx.z : 3;

    const __half* pA = (MODE == 0) ? g_x : g_ctx;
    const __half* pB = g_W + (size_t)z * Dd * Dd;

    const int q  = tid & 7;
    const int rs = tid >> 3;

    auto issue = [&](int ch, int st) {
        const int k0 = ch * 64 + q * 8;
        const uint32_t stb = sb + (uint32_t)st * G_STAGE;
#pragma unroll
        for (int j = 0; j < 4; j++) {
            int row = j * 32 + rs;
            uint32_t so = swz(row, q * 16);
            cp16(stb + so,         pA + (size_t)(m0 + row) * Dd + k0);
            cp16(stb + 16384 + so, pB + (size_t)(n0 + row) * Dd + k0);
        }
        CP_COMMIT();
    };

    float acc[4][4][4];
#pragma unroll
    for (int a = 0; a < 4; a++)
#pragma unroll
        for (int b = 0; b < 4; b++)
#pragma unroll
            for (int c = 0; c < 4; c++) acc[a][b][c] = 0.0f;

    issue(0, 0);
    issue(1, 1);

    constexpr int NCH = Dd / 64;   // 16
    for (int ch = 0; ch < NCH; ch++) {
        if (ch < NCH - 1) CP_WAIT1(); else CP_WAIT0();
        __syncthreads();     // also proves compute(ch-1) done -> stage reuse safe
        if (ch + 2 < NCH) issue(ch + 2, (ch + 2) % 3);

        const uint32_t aA = sb + (uint32_t)(ch % 3) * G_STAGE;
        const uint32_t aB = aA + 16384;

#pragma unroll
        for (int ks = 0; ks < 4; ks++) {
            uint32_t bh[2][4];
            const int g = lane >> 3;
            const int brow = wn * 32 + ((g >> 1) << 3) + (lane & 7);
            const int bqb = ks * 32 + ((g & 1) << 4);
#pragma unroll
            for (int p = 0; p < 2; p++)
                ldsm4(bh[p], aB + swz(brow + p * 16, bqb));

            const int arow = wm * 64 + (lane & 15);
            const int aqb = ks * 32 + ((lane >> 4) << 4);
#pragma unroll
            for (int mt = 0; mt < 4; mt++) {
                uint32_t ah[4];
                ldsm4(ah, aA + swz(arow + mt * 16, aqb));
#pragma unroll
                for (int p = 0; p < 2; p++) {
                    mma16816(acc[mt][2 * p],     ah, &bh[p][0]);
                    mma16816(acc[mt][2 * p + 1], ah, &bh[p][2]);
                }
            }
        }
    }

    // epilogue
    const int g4 = lane >> 2, q2 = (lane & 3) * 2;
#pragma unroll
    for (int mt = 0; mt < 4; mt++)
#pragma unroll
        for (int nt = 0; nt < 4; nt++) {
            int r0 = m0 + wm * 64 + mt * 16 + g4;
            int n  = n0 + wn * 32 + nt * 8 + q2;
            if (MODE == 1) {
                float b0 = bias[n], b1 = bias[n + 1];
                float2 v0 = {acc[mt][nt][0] + b0, acc[mt][nt][1] + b1};
                float2 v1 = {acc[mt][nt][2] + b0, acc[mt][nt][3] + b1};
                *(float2*)&outd[(size_t)r0 * Dd + n] = v0;
                *(float2*)&outd[(size_t)(r0 + 8) * Dd + n] = v1;
            } else {
                __half* ob = (z == 0) ? g_Q : (z == 1) ? g_K : g_V;
                int b = r0 >> 11, s = r0 & 2047;
                int h = n >> 6,  d = n & 63;
                size_t i0 = (((size_t)(b * Hh + h)) * Ss + s) * HD + d;
                size_t i1 = i0 + (size_t)8 * HD;
                *(uint32_t*)&ob[i0] = pack2h(acc[mt][nt][0], acc[mt][nt][1]);
                *(uint32_t*)&ob[i1] = pack2h(acc[mt][nt][2], acc[mt][nt][3]);
            }
        }
}

// ---------------------------------------------------------------------------
// 3) flash: q-tile 128 (256 thr, 8 warps), k-tile 64, all single fp16.
//    3-stage cp.async K/V, single barrier per k-tile, 2 CTAs/SM.
// smem: Q 16K + 3 stages x {K, V} 8K each = 64K.
// ---------------------------------------------------------------------------
constexpr int F_Q   = 16384;
constexpr int F_KV  = 8192;
constexpr int FLASH_SMEM = F_Q + 6 * F_KV;   // 65536

__global__ __launch_bounds__(256, 2) void flash_tc()
{
    extern __shared__ char fsc[];
    const uint32_t sb = smaddr(fsc);

    const int tid = threadIdx.x, lane = tid & 31, wid = tid >> 5;
    const int qt = gridDim.x - 1 - blockIdx.x;     // heavy tiles first
    const int bhi = blockIdx.y;
    const size_t base = (size_t)bhi * Ss * HD;
    const float SCL = 0.125f * 1.4426950408889634f;

    const __half* ksrc[2] = {g_K + base, g_V + base};

    const int q  = tid & 7;
    const int rs = tid >> 3;

    auto issue_kv = [&](int kt, int st) {
        const uint32_t stb = sb + F_Q + (uint32_t)st * 2 * F_KV;
#pragma unroll
        for (int a = 0; a < 2; a++) {
#pragma unroll
            for (int j = 0; j < 2; j++) {
                int row = j * 32 + rs;
                cp16(stb + (uint32_t)a * F_KV + swz(row, q * 16),
                     ksrc[a] + (size_t)(kt * 64 + row) * HD + q * 8);
            }
        }
        CP_COMMIT();
    };

    const int ktmax = 2 * qt + 1;
    issue_kv(0, 0);
    issue_kv(1, 1);

    // Q tile: 128 rows x 64 fp16
#pragma unroll
    for (int j = 0; j < 4; j++) {
        int row = j * 32 + rs;
        size_t go = base + (size_t)(qt * 128 + row) * HD + q * 8;
        *(uint4*)(fsc + swz(row, q * 16)) = *(const uint4*)&g_Q[go];
    }

    float m0_ = -1e30f, m1_ = -1e30f, l0_ = 0.f, l1_ = 0.f;
    float o[8][4];
#pragma unroll
    for (int t = 0; t < 8; t++)
#pragma unroll
        for (int c = 0; c < 4; c++) o[t][c] = 0.f;

    const uint32_t aQ = sb;

    for (int kt = 0; kt <= ktmax; kt++) {
        if (kt < ktmax) CP_WAIT1(); else CP_WAIT0();
        __syncthreads();   // also proves compute(kt-1) done -> stage reuse safe
        if (kt + 2 <= ktmax) issue_kv(kt + 2, (kt + 2) % 3);

        const uint32_t stb = sb + F_Q + (uint32_t)(kt % 3) * 2 * F_KV;
        const uint32_t aK = stb, aV = stb + F_KV;

        // S = Q K^T (single)
        float s[8][4];
#pragma unroll
        for (int t = 0; t < 8; t++)
#pragma unroll
            for (int c = 0; c < 4; c++) s[t][c] = 0.f;

#pragma unroll
        for (int ks = 0; ks < 4; ks++) {
            uint32_t qh[4];
            const int arow = wid * 16 + (lane & 15);
            const int aqb  = ks * 32 + ((lane >> 4) << 4);
            ldsm4(qh, aQ + swz(arow, aqb));
            const int g = lane >> 3;
            const int br = ((g >> 1) << 3) + (lane & 7);
            const int bqb = ks * 32 + ((g & 1) << 4);
#pragma unroll
            for (int p = 0; p < 4; p++) {
                uint32_t kh[4];
                ldsm4(kh, aK + swz(br + p * 16, bqb));
                mma16816(s[2 * p],     qh, &kh[0]);
                mma16816(s[2 * p + 1], qh, &kh[2]);
            }
        }

        // scale (base-2) + causal mask (last two k-tiles only)
        const int r0g = qt * 128 + wid * 16 + (lane >> 2);
        const int r1g = r0g + 8;
        const bool needmask = (kt >= 2 * qt);
        float mx0 = -1e30f, mx1 = -1e30f;
#pragma unroll
        for (int t = 0; t < 8; t++) {
            int cg = kt * 64 + t * 8 + (lane & 3) * 2;
            float v0 = s[t][0] * SCL, v1 = s[t][1] * SCL;
            float v2 = s[t][2] * SCL, v3 = s[t][3] * SCL;
            if (needmask) {
                if (cg     > r0g) v0 = -1e30f;
                if (cg + 1 > r0g) v1 = -1e30f;
                if (cg     > r1g) v2 = -1e30f;
                if (cg + 1 > r1g) v3 = -1e30f;
            }
            s[t][0] = v0; s[t][1] = v1; s[t][2] = v2; s[t][3] = v3;
            mx0 = fmaxf(mx0, fmaxf(v0, v1));
            mx1 = fmaxf(mx1, fmaxf(v2, v3));
        }
        mx0 = fmaxf(mx0, __shfl_xor_sync(0xffffffffu, mx0, 1));
        mx0 = fmaxf(mx0, __shfl_xor_sync(0xffffffffu, mx0, 2));
        mx1 = fmaxf(mx1, __shfl_xor_sync(0xffffffffu, mx1, 1));
        mx1 = fmaxf(mx1, __shfl_xor_sync(0xffffffffu, mx1, 2));
        float nm0 = fmaxf(m0_, mx0), nm1 = fmaxf(m1_, mx1);
        float al0 = ex2f(m0_ - nm0), al1 = ex2f(m1_ - nm1);
        float sum0 = 0.f, sum1 = 0.f;
#pragma unroll
        for (int t = 0; t < 8; t++) {
            float p0 = ex2f(s[t][0] - nm0), p1 = ex2f(s[t][1] - nm0);
            float p2 = ex2f(s[t][2] - nm1), p3 = ex2f(s[t][3] - nm1);
            s[t][0] = p0; s[t][1] = p1; s[t][2] = p2; s[t][3] = p3;
            sum0 += p0 + p1; sum1 += p2 + p3;
        }
        sum0 += __shfl_xor_sync(0xffffffffu, sum0, 1);
        sum0 += __shfl_xor_sync(0xffffffffu, sum0, 2);
        sum1 += __shfl_xor_sync(0xffffffffu, sum1, 1);
        sum1 += __shfl_xor_sync(0xffffffffu, sum1, 2);
        l0_ = l0_ * al0 + sum0;
        l1_ = l1_ * al1 + sum1;
        m0_ = nm0; m1_ = nm1;
#pragma unroll
        for (int t = 0; t < 8; t++) {
            o[t][0] *= al0; o[t][1] *= al0;
            o[t][2] *= al1; o[t][3] *= al1;
        }

        // pack P (single fp16) into A-fragments
        uint32_t pa[4][4];
#pragma unroll
        for (int t = 0; t < 4; t++) {
            pa[t][0] = pack2h(s[2 * t][0],     s[2 * t][1]);
            pa[t][1] = pack2h(s[2 * t][2],     s[2 * t][3]);
            pa[t][2] = pack2h(s[2 * t + 1][0], s[2 * t + 1][1]);
            pa[t][3] = pack2h(s[2 * t + 1][2], s[2 * t + 1][3]);
        }

        // O += P V (single), V via ldmatrix.trans
        const int g = lane >> 3;
        const int vr = ((g & 1) << 3) + (lane & 7);
        const int vcb = (lane >= 16) ? 16 : 0;
#pragma unroll
        for (int t = 0; t < 4; t++) {
            int r = t * 16 + vr;
#pragma unroll
            for (int dp = 0; dp < 4; dp++) {
                uint32_t vh[4];
                ldsm4t(vh, aV + swz(r, dp * 32 + vcb));
                mma16816(o[2 * dp],     pa[t], &vh[0]);
                mma16816(o[2 * dp + 1], pa[t], &vh[2]);
            }
        }
        // no trailing barrier: next iteration's top __syncthreads covers reuse
    }

    // epilogue: normalize, single fp16 ctx [B*S, D]
    const int b = bhi >> 4, h = bhi & 15;
    const float i0 = 1.f / l0_, i1 = 1.f / l1_;
    const int r0 = qt * 128 + wid * 16 + (lane >> 2);
    const size_t row0 = (size_t)(b * Ss + r0) * Dd;
    const size_t row1 = row0 + (size_t)8 * Dd;
#pragma unroll
    for (int dt = 0; dt < 8; dt++) {
        int d = h * 64 + dt * 8 + (lane & 3) * 2;
        *(uint32_t*)&g_ctx[row0 + d] = pack2h(o[dt][0] * i0, o[dt][1] * i0);
        *(uint32_t*)&g_ctx[row1 + d] = pack2h(o[dt][2] * i1, o[dt][3] * i1);
    }
}

// ---------------------------------------------------------------------------
extern "C" void kernel_launch(void* const* d_in, const int* in_sizes, int n_in,
                              void* d_out, int out_size)
{
    const float* x  = (const float*)d_in[0];
    const float* Wq = (const float*)d_in[1];
    const float* Wk = (const float*)d_in[2];
    const float* Wv = (const float*)d_in[3];
    const float* Wo = (const float*)d_in[4];
    const float* bo = (const float*)d_in[5];
    float* out = (float*)d_out;

    cudaFuncSetAttribute(gemm_tc<0>, cudaFuncAttributeMaxDynamicSharedMemorySize,
                         GEMM_SMEM);
    cudaFuncSetAttribute(gemm_tc<1>, cudaFuncAttributeMaxDynamicSharedMemorySize,
                         GEMM_SMEM);
    cudaFuncSetAttribute(flash_tc, cudaFuncAttributeMaxDynamicSharedMemorySize,
                         FLASH_SMEM);

    // 1) x, W -> single fp16
    convert_fp16<<<(Mm * Dd / 4 + 4 * Dd * Dd / 4 + 255) / 256, 256>>>(
        x, Wq, Wk, Wv, Wo);

    // 2) Q/K/V projections (one launch, z selects weight + output)
    gemm_tc<0><<<dim3(Dd / 128, Mm / 128, 3), 256, GEMM_SMEM>>>(nullptr, nullptr);

    // 3) causal flash attention (q-tile 128, heavy-first)
    flash_tc<<<dim3(Ss / 128, Bb * Hh), 256, FLASH_SMEM>>>();

    // 4) output projection + bias
    gemm_tc<1><<<dim3(Dd / 128, Mm / 128, 1), 256, GEMM_SMEM>>>(bo, out);
}